// round 12
// baseline (speedup 1.0000x reference)
#include <cuda_runtime.h>
#include <cuda_bf16.h>
#include <math.h>
#include <stdint.h>

// ---------------- problem constants ----------------
#define B_    4
#define S_    2048
#define H_    768
#define NH_   8
#define DH_   96
#define L_    128
#define ML_   15
#define LM_   1920      // L_*ML_
#define QKV_  2304      // 3*H_

// ---------------- scratch ----------------
__device__ __nv_bfloat16 g_hb  [(size_t)B_ * S_ * H_];
__device__ __nv_bfloat16 g_wib [(size_t)QKV_ * H_];
__device__ __nv_bfloat16 g_wob [(size_t)H_ * H_];
__device__ __nv_bfloat16 g_qkvh[(size_t)B_ * S_ * QKV_];   // Q pre-scaled
__device__ __nv_bfloat16 g_atnh[(size_t)B_ * LM_ * H_];
__device__ float g_oproj[(size_t)B_ * LM_ * H_];
__device__ float g_x    [(size_t)B_ * L_ * 2 * H_];
__device__ float g_y1   [(size_t)B_ * L_ * H_];
__device__ float g_y2   [(size_t)B_ * L_ * H_];

// ---------------- helpers ----------------
__device__ __forceinline__ unsigned pk(float lo, float hi) {
    unsigned r;
    asm("cvt.rn.bf16x2.f32 %0, %1, %2;" : "=r"(r) : "f"(hi), "f"(lo));
    return r;
}
__device__ __forceinline__ unsigned bex2(unsigned x) {
    unsigned r;
    asm("ex2.approx.ftz.bf16x2 %0, %1;" : "=r"(r) : "r"(x));
    return r;
}
__device__ __forceinline__ void mma_bf16(float* d, const unsigned* a, const unsigned* b) {
    asm volatile(
        "mma.sync.aligned.m16n8k16.row.col.f32.bf16.bf16.f32 "
        "{%0,%1,%2,%3}, {%4,%5,%6,%7}, {%8,%9}, {%0,%1,%2,%3};"
        : "+f"(d[0]), "+f"(d[1]), "+f"(d[2]), "+f"(d[3])
        : "r"(a[0]), "r"(a[1]), "r"(a[2]), "r"(a[3]), "r"(b[0]), "r"(b[1]));
}
__device__ __forceinline__ void mma_tf32(float* d, const unsigned* a, const unsigned* b) {
    asm volatile(
        "mma.sync.aligned.m16n8k8.row.col.f32.tf32.tf32.f32 "
        "{%0,%1,%2,%3}, {%4,%5,%6,%7}, {%8,%9}, {%0,%1,%2,%3};"
        : "+f"(d[0]), "+f"(d[1]), "+f"(d[2]), "+f"(d[3])
        : "r"(a[0]), "r"(a[1]), "r"(a[2]), "r"(a[3]), "r"(b[0]), "r"(b[1]));
}
__device__ __forceinline__ uint32_t s2u(const void* p) {
    uint32_t a;
    asm("{ .reg .u64 t; cvta.to.shared.u64 t, %1; cvt.u32.u64 %0, t; }" : "=r"(a) : "l"(p));
    return a;
}
__device__ __forceinline__ void cpa16(uint32_t s, const void* g) {
    asm volatile("cp.async.cg.shared.global [%0], [%1], 16;" :: "r"(s), "l"(g));
}
#define CP_COMMIT() asm volatile("cp.async.commit_group;")
#define CP_WAIT2()  asm volatile("cp.async.wait_group 2;")
__device__ __forceinline__ void ldm4(uint4& d, uint32_t a) {
    asm volatile("ldmatrix.sync.aligned.m8n8.x4.shared.b16 {%0,%1,%2,%3}, [%4];"
                 : "=r"(d.x), "=r"(d.y), "=r"(d.z), "=r"(d.w) : "r"(a));
}
__device__ __forceinline__ void ldm4t(uint4& d, uint32_t a) {
    asm volatile("ldmatrix.sync.aligned.m8n8.x4.trans.shared.b16 {%0,%1,%2,%3}, [%4];"
                 : "=r"(d.x), "=r"(d.y), "=r"(d.z), "=r"(d.w) : "r"(a));
}

// ---------------- f32 -> bf16 convert ----------------
__global__ __launch_bounds__(256) void f2b_kernel(
    const float* __restrict__ src, __nv_bfloat16* __restrict__ dst, int n2)
{
    int stride = gridDim.x * blockDim.x;
    for (int i = blockIdx.x * blockDim.x + threadIdx.x; i < n2; i += stride) {
        float2 v = ((const float2*)src)[i];
        ((unsigned*)dst)[i] = pk(v.x, v.y);
    }
}

// ---------------- bf16 NT GEMM: cp.async 3-stage + ldmatrix ----------------
__global__ __launch_bounds__(256) void gemm_bf16_cp(
    const __nv_bfloat16* __restrict__ A, const __nv_bfloat16* __restrict__ Bw,
    const float* __restrict__ bias, void* __restrict__ Cout,
    int M, int N, int K, int out_bf16, float qmul, int qcols)
{
    __shared__ __align__(16) char smem[3 * 16384];

    int tid = threadIdx.x;
    int warp = tid >> 5, lane = tid & 31;
    int warp_m = warp >> 1, warp_n = warp & 1;
    int m0 = blockIdx.y * 128, n0 = blockIdx.x * 128;
    uint32_t sbase = s2u(smem);

    float acc[2][8][4];
#pragma unroll
    for (int mi = 0; mi < 2; mi++)
#pragma unroll
        for (int ni = 0; ni < 8; ni++)
#pragma unroll
            for (int r = 0; r < 4; r++) acc[mi][ni][r] = 0.0f;

    int nslab = K >> 5;
    int frow0 = tid >> 2,        fc0 = tid & 3;
    int frow1 = (tid + 256) >> 2, fc1 = (tid + 256) & 3;

#define FILL(st, sl)                                                                   \
    do {                                                                               \
        int k0f = (sl) << 5;                                                           \
        uint32_t sa = sbase + (st) * 16384;                                            \
        uint32_t sb = sa + 8192;                                                       \
        cpa16(sa + (frow0 * 4 + (fc0 ^ ((frow0 >> 1) & 3))) * 16,                      \
              A + (size_t)(m0 + frow0) * K + k0f + fc0 * 8);                           \
        cpa16(sa + (frow1 * 4 + (fc1 ^ ((frow1 >> 1) & 3))) * 16,                      \
              A + (size_t)(m0 + frow1) * K + k0f + fc1 * 8);                           \
        cpa16(sb + (frow0 * 4 + (fc0 ^ ((frow0 >> 1) & 3))) * 16,                      \
              Bw + (size_t)(n0 + frow0) * K + k0f + fc0 * 8);                          \
        cpa16(sb + (frow1 * 4 + (fc1 ^ ((frow1 >> 1) & 3))) * 16,                      \
              Bw + (size_t)(n0 + frow1) * K + k0f + fc1 * 8);                          \
    } while (0)

    FILL(0, 0); CP_COMMIT();
    if (nslab > 1) FILL(1, 1);
    CP_COMMIT();

    for (int i = 0; i < nslab; i++) {
        if (i + 2 < nslab) FILL((i + 2) % 3, i + 2);
        CP_COMMIT();
        CP_WAIT2();
        __syncthreads();

        uint32_t sa = sbase + (i % 3) * 16384;
        uint32_t sb = sa + 8192;
#pragma unroll
        for (int ks = 0; ks < 2; ks++) {
            uint4 afr[2];
#pragma unroll
            for (int mi = 0; mi < 2; mi++) {
                int row = warp_m * 32 + mi * 16 + ((lane >> 3) & 1) * 8 + (lane & 7);
                int ch = ks * 2 + (lane >> 4);
                ldm4(afr[mi], sa + (row * 4 + (ch ^ ((row >> 1) & 3))) * 16);
            }
            uint4 bfr[4];
#pragma unroll
            for (int nj = 0; nj < 4; nj++) {
                int row = warp_n * 64 + nj * 16 + ((lane >> 4) & 1) * 8 + (lane & 7);
                int ch = ks * 2 + ((lane >> 3) & 1);
                ldm4(bfr[nj], sb + (row * 4 + (ch ^ ((row >> 1) & 3))) * 16);
            }
#pragma unroll
            for (int mi = 0; mi < 2; mi++)
#pragma unroll
                for (int nj = 0; nj < 4; nj++) {
                    mma_bf16(acc[mi][2 * nj],     (const unsigned*)&afr[mi], &bfr[nj].x);
                    mma_bf16(acc[mi][2 * nj + 1], (const unsigned*)&afr[mi], &bfr[nj].z);
                }
        }
        __syncthreads();
    }
#undef FILL

#pragma unroll
    for (int mi = 0; mi < 2; mi++) {
        int row = m0 + warp_m * 32 + mi * 16 + (lane >> 2);
#pragma unroll
        for (int ni = 0; ni < 8; ni++) {
            int col = n0 + warp_n * 64 + ni * 8 + ((lane & 3) << 1);
            float b0 = bias ? bias[col] : 0.0f;
            float b1 = bias ? bias[col + 1] : 0.0f;
            float v0 = acc[mi][ni][0] + b0, v1 = acc[mi][ni][1] + b1;
            float v2 = acc[mi][ni][2] + b0, v3 = acc[mi][ni][3] + b1;
            if (out_bf16) {
                float s = (col < qcols) ? qmul : 1.0f;
                __nv_bfloat16* Cb = (__nv_bfloat16*)Cout;
                *(unsigned*)(Cb + (size_t)row * N + col)       = pk(v0 * s, v1 * s);
                *(unsigned*)(Cb + (size_t)(row + 8) * N + col) = pk(v2 * s, v3 * s);
            } else {
                float* Cf = (float*)Cout;
                *(float2*)(Cf + (size_t)row * N + col)       = make_float2(v0, v1);
                *(float2*)(Cf + (size_t)(row + 8) * N + col) = make_float2(v2, v3);
            }
        }
    }
}

// ---------------- tf32 NT GEMM (classifier) ----------------
__global__ __launch_bounds__(256) void gemm_tf32_nt(
    const float* __restrict__ A, const float* __restrict__ Bw,
    const float* __restrict__ bias, float* __restrict__ C,
    int M, int N, int K)
{
    __shared__ unsigned As[4 * 8 * 128];
    __shared__ unsigned Bs[4 * 16 * 64];

    int tid = threadIdx.x;
    int warp = tid >> 5, lane = tid & 31;
    int warp_m = warp >> 1, warp_n = warp & 1;
    int m0 = blockIdx.y * 128, n0 = blockIdx.x * 128;

    float acc[2][8][4];
#pragma unroll
    for (int mi = 0; mi < 2; mi++)
#pragma unroll
        for (int ni = 0; ni < 8; ni++)
#pragma unroll
            for (int r = 0; r < 4; r++) acc[mi][ni][r] = 0.0f;

    for (int k0 = 0; k0 < K; k0 += 32) {
        __syncthreads();
#pragma unroll
        for (int i = 0; i < 4; i++) {
            int f = tid + i * 256;
            int row = f >> 3, kq = f & 7;
            float4 v = *(const float4*)(A + (size_t)(m0 + row) * K + k0 + kq * 4);
            int mtile = row >> 4, r = row & 15, ktile = kq >> 1;
            int regb = (r >> 3) + ((kq & 1) << 1);
            unsigned* p = &As[((ktile * 8 + mtile) * 32 + (r & 7) * 4) * 4 + regb];
            p[0]  = __float_as_uint(v.x);
            p[4]  = __float_as_uint(v.y);
            p[8]  = __float_as_uint(v.z);
            p[12] = __float_as_uint(v.w);
        }
#pragma unroll
        for (int i = 0; i < 4; i++) {
            int f = tid + i * 256;
            int row = f >> 3, kq = f & 7;
            float4 v = *(const float4*)(Bw + (size_t)(n0 + row) * K + k0 + kq * 4);
            int ntile = row >> 3, ktile = kq >> 1, reg = kq & 1;
            unsigned* p = &Bs[(ktile * 16 + ntile) * 64 + (row & 7) * 8 + reg];
            p[0] = __float_as_uint(v.x);
            p[2] = __float_as_uint(v.y);
            p[4] = __float_as_uint(v.z);
            p[6] = __float_as_uint(v.w);
        }
        __syncthreads();
#pragma unroll
        for (int ks = 0; ks < 4; ks++) {
            uint4 a[2];
            uint2 b[8];
#pragma unroll
            for (int mi = 0; mi < 2; mi++)
                a[mi] = *(const uint4*)&As[((ks * 8 + warp_m * 2 + mi) * 32 + lane) * 4];
#pragma unroll
            for (int ni = 0; ni < 8; ni++)
                b[ni] = *(const uint2*)&Bs[((ks * 16 + warp_n * 8 + ni) * 32 + lane) * 2];
#pragma unroll
            for (int mi = 0; mi < 2; mi++)
#pragma unroll
                for (int ni = 0; ni < 8; ni++)
                    mma_tf32(acc[mi][ni], (const unsigned*)&a[mi], (const unsigned*)&b[ni]);
        }
    }

#pragma unroll
    for (int mi = 0; mi < 2; mi++) {
        int row = m0 + warp_m * 32 + mi * 16 + (lane >> 2);
#pragma unroll
        for (int ni = 0; ni < 8; ni++) {
            int col = n0 + warp_n * 64 + ni * 8 + ((lane & 3) << 1);
            float b0 = bias ? bias[col] : 0.0f;
            float b1 = bias ? bias[col + 1] : 0.0f;
            *(float2*)(C + (size_t)row * N + col)       = make_float2(acc[mi][ni][0] + b0, acc[mi][ni][1] + b1);
            *(float2*)(C + (size_t)(row + 8) * N + col) = make_float2(acc[mi][ni][2] + b0, acc[mi][ni][3] + b1);
        }
    }
}

// ---------------- bf16 flash cross-attention: 4-stage pipeline, 1 sync/chunk ----------------
#define AST 24576   // per-stage: K 12288 + V 12288
#define NSTG 4
__global__ __launch_bounds__(256, 2) void attn_kernel(
    const __nv_bfloat16* __restrict__ qkv,
    const int* __restrict__ line_starts,
    const int* __restrict__ ctx_len,
    __nv_bfloat16* __restrict__ out)
{
    extern __shared__ __align__(16) char smem[];   // NSTG * AST = 96KB dynamic

    int tid = threadIdx.x;
    int warp = tid >> 5, lane = tid & 31;
    int b = blockIdx.z, h = blockIdx.y, q0 = blockIdx.x * 128;
    uint32_t sb = s2u(smem);

    int r0 = warp * 16 + (lane >> 2);
    int c2 = (lane & 3) * 2;
    int ctx = ctx_len[b];

    // ---- Q fragments straight from gmem (bf16, pre-scaled by scale*log2e) ----
    const __nv_bfloat16 *qp0, *qp1;
    {
        int gq0 = q0 + r0;
        int l0i = gq0 / ML_, mm0 = gq0 - l0i * ML_;
        int pos0 = min(max(line_starts[b * L_ + l0i] + mm0, 0), S_ - 1);
        int gq1 = gq0 + 8;
        int l1i = gq1 / ML_, mm1 = gq1 - l1i * ML_;
        int pos1 = min(max(line_starts[b * L_ + l1i] + mm1, 0), S_ - 1);
        qp0 = qkv + ((size_t)b * S_ + pos0) * QKV_ + h * DH_;
        qp1 = qkv + ((size_t)b * S_ + pos1) * QKV_ + h * DH_;
    }
    unsigned qf[6][4];
#pragma unroll
    for (int ks = 0; ks < 6; ks++) {
        qf[ks][0] = *(const unsigned*)(qp0 + ks * 16 + c2);
        qf[ks][1] = *(const unsigned*)(qp1 + ks * 16 + c2);
        qf[ks][2] = *(const unsigned*)(qp0 + ks * 16 + c2 + 8);
        qf[ks][3] = *(const unsigned*)(qp1 + ks * 16 + c2 + 8);
    }

    // ---- per-thread fill coords ----
    const __nv_bfloat16 *kg[3], *vg[3];
    int foff[3];
#pragma unroll
    for (int i = 0; i < 3; i++) {
        int u = tid + i * 256;
        int row = u / 12, c = u - row * 12;
        foff[i] = row * 192 + (c ^ ((row >> 1) & 3)) * 16;
        kg[i] = qkv + ((size_t)b * S_ + row) * QKV_ + H_ + h * DH_ + c * 8;
        vg[i] = kg[i] + H_;
    }

    // ---- per-thread ldmatrix coords ----
    int sm = lane >> 3;
    int srow = (sm >> 1) * 8 + (lane & 7);
    int scb = sm & 1;
    int sprow[4], spsw[4];
#pragma unroll
    for (int np = 0; np < 4; np++) {
        int row = np * 16 + srow;
        sprow[np] = row * 192;
        spsw[np] = (row >> 1) & 3;
    }
    int vrow_b = (sm & 1) * 8 + (lane & 7);
    int vcb = sm >> 1;
    int vprow[4], vpsw[4];
#pragma unroll
    for (int ks = 0; ks < 4; ks++) {
        int row = ks * 16 + vrow_b;
        vprow[ks] = row * 192;
        vpsw[ks] = (row >> 1) & 3;
    }

    const unsigned bones[2] = {0x3F803F80u, 0x3F803F80u};

    float Oacc[12][4], lacc[4];
#pragma unroll
    for (int nt = 0; nt < 12; nt++)
#pragma unroll
        for (int r = 0; r < 4; r++) Oacc[nt][r] = 0.0f;
#pragma unroll
    for (int r = 0; r < 4; r++) lacc[r] = 0.0f;

#define AFILL(st, s0f)                                                          \
    do {                                                                        \
        uint32_t kb_ = sb + (st) * AST;                                         \
        uint32_t vb_ = kb_ + 12288;                                             \
        _Pragma("unroll")                                                       \
        for (int i_ = 0; i_ < 3; i_++) {                                        \
            cpa16(kb_ + foff[i_], kg[i_] + (size_t)(s0f) * QKV_);               \
            cpa16(vb_ + foff[i_], vg[i_] + (size_t)(s0f) * QKV_);               \
        }                                                                       \
    } while (0)

    // prologue: fill stages 0,1,2 (chunks 0,1,2)
    AFILL(0, 0);   CP_COMMIT();
    AFILL(1, 64);  CP_COMMIT();
    AFILL(2, 128); CP_COMMIT();

    for (int ci = 0; ci < 32; ci++) {
        int s0 = ci * 64;
        CP_WAIT2();            // stage ci resident (<=2 younger groups pending)
        __syncthreads();       // all warps' copies visible; prior-stage reads done

        // fill stage (ci+3)%4 — overwrites stage read at ci-1, safe post-sync
        if (ci + 3 < 32) AFILL((ci + 3) & 3, s0 + 192);
        CP_COMMIT();

        uint32_t Kst = sb + (ci & 3) * AST;
        uint32_t Vst = Kst + 12288;

        // ---- scores: 16q x 64tok per warp ----
        float sacc[8][4];
#pragma unroll
        for (int nt = 0; nt < 8; nt++)
#pragma unroll
            for (int r = 0; r < 4; r++) sacc[nt][r] = 0.0f;
#pragma unroll
        for (int ks = 0; ks < 6; ks++) {
#pragma unroll
            for (int np = 0; np < 4; np++) {
                uint4 kb;
                ldm4(kb, Kst + sprow[np] + ((2 * ks + scb) ^ spsw[np]) * 16);
                mma_bf16(sacc[2 * np],     qf[ks], &kb.x);
                mma_bf16(sacc[2 * np + 1], qf[ks], &kb.z);
            }
        }

        // ---- mask only boundary chunks ----
        if (s0 + 64 > ctx) {
#pragma unroll
            for (int nt = 0; nt < 8; nt++) {
                int t = s0 + nt * 8 + c2;
                if (t >= ctx)     { sacc[nt][0] = -3e38f; sacc[nt][2] = -3e38f; }
                if (t + 1 >= ctx) { sacc[nt][1] = -3e38f; sacc[nt][3] = -3e38f; }
            }
        }

        // ---- fixed-base exp + P@V (+ l via ones frag) ----
#pragma unroll
        for (int ks = 0; ks < 4; ks++) {
            unsigned pa[4];
            pa[0] = bex2(pk(sacc[2 * ks][0],     sacc[2 * ks][1]));
            pa[1] = bex2(pk(sacc[2 * ks][2],     sacc[2 * ks][3]));
            pa[2] = bex2(pk(sacc[2 * ks + 1][0], sacc[2 * ks + 1][1]));
            pa[3] = bex2(pk(sacc[2 * ks + 1][2], sacc[2 * ks + 1][3]));
            mma_bf16(lacc, pa, bones);
#pragma unroll
            for (int np = 0; np < 6; np++) {
                uint4 vb;
                ldm4t(vb, Vst + vprow[ks] + ((2 * np + vcb) ^ vpsw[ks]) * 16);
                mma_bf16(Oacc[2 * np],     pa, &vb.x);
                mma_bf16(Oacc[2 * np + 1], pa, &vb.z);
            }
        }
    }
#undef AFILL

    // ---- epilogue ----
    float inv0 = 1.0f / lacc[0];
    float inv1 = 1.0f / lacc[2];
#pragma unroll
    for (int nt = 0; nt < 12; nt++) {
        int col = h * DH_ + nt * 8 + c2;
        *(unsigned*)(out + ((size_t)b * LM_ + q0 + r0) * H_ + col) =
            pk(Oacc[nt][0] * inv0, Oacc[nt][1] * inv0);
        *(unsigned*)(out + ((size_t)b * LM_ + q0 + r0 + 8) * H_ + col) =
            pk(Oacc[nt][2] * inv1, Oacc[nt][3] * inv1);
    }
}

// ---------------- masked mean-pool ----------------
__global__ __launch_bounds__(256) void pool_kernel(
    const float* __restrict__ hidden, const float* __restrict__ oproj,
    const int* __restrict__ line_starts, const int* __restrict__ line_lens,
    float* __restrict__ x)
{
    int bl = blockIdx.x;
    int b = bl / L_;
    int len = line_lens[bl];
    int start = line_starts[bl];
    float inv = 1.0f / (float)max(len, 1);
    for (int c = threadIdx.x; c < H_; c += 256) {
        float s1 = 0.0f, s2 = 0.0f;
        for (int m = 0; m < ML_; m++) {
            if (m < len) {
                int pos = min(max(start + m, 0), S_ - 1);
                s1 += hidden[((size_t)b * S_ + pos) * H_ + c];
                s2 += oproj[((size_t)bl * ML_ + m) * H_ + c];
            }
        }
        x[(size_t)bl * 2 * H_ + c]      = s1 * inv;
        x[(size_t)bl * 2 * H_ + H_ + c] = s2 * inv;
    }
}

// ---------------- LayerNorm -> exact GELU (+optional residual) ----------------
__global__ __launch_bounds__(256) void ln_gelu_kernel(
    const float* __restrict__ y, const float* __restrict__ g,
    const float* __restrict__ be, const float* __restrict__ res,
    float* __restrict__ out)
{
    __shared__ float red1[8], red2[8];
    int row = blockIdx.x;
    const float* yr = y + (size_t)row * H_;
    float v[3], sum = 0.0f, sq = 0.0f;
#pragma unroll
    for (int i = 0; i < 3; i++) {
        v[i] = yr[threadIdx.x + 256 * i];
        sum += v[i];
        sq  += v[i] * v[i];
    }
#pragma unroll
    for (int o = 16; o > 0; o >>= 1) {
        sum += __shfl_xor_sync(0xffffffffu, sum, o);
        sq  += __shfl_xor_sync(0xffffffffu, sq,  o);
    }
    int warp = threadIdx.x >> 5;
    if ((threadIdx.x & 31) == 0) { red1[warp] = sum; red2[warp] = sq; }
    __syncthreads();
    float tsum = 0.0f, tsq = 0.0f;
#pragma unroll
    for (int i = 0; i < 8; i++) { tsum += red1[i]; tsq += red2[i]; }
    float mean = tsum * (1.0f / H_);
    float var  = tsq  * (1.0f / H_) - mean * mean;
    float rstd = rsqrtf(var + 1e-5f);
#pragma unroll
    for (int i = 0; i < 3; i++) {
        int c = threadIdx.x + 256 * i;
        float t  = (v[i] - mean) * rstd * g[c] + be[c];
        float ge = 0.5f * t * (1.0f + erff(t * 0.70710678118654752f));
        out[(size_t)row * H_ + c] = (res ? res[(size_t)row * H_ + c] : 0.0f) + ge;
    }
}

// ---------------- final logit ----------------
__global__ __launch_bounds__(128) void final_kernel(
    const float* __restrict__ a2, const float* __restrict__ W3,
    const float* __restrict__ b3, const int* __restrict__ line_lens,
    float* __restrict__ out)
{
    int row  = blockIdx.x * 4 + (threadIdx.x >> 5);
    int lane = threadIdx.x & 31;
    float s = 0.0f;
    for (int c = lane; c < H_; c += 32)
        s += a2[(size_t)row * H_ + c] * W3[c];
#pragma unroll
    for (int o = 16; o > 0; o >>= 1) s += __shfl_xor_sync(0xffffffffu, s, o);
    if (lane == 0) {
        float logit = s + b3[0];
        if (line_lens[row] <= 0) logit = -10.0f;
        out[row] = 1.0f / (1.0f + __expf(-logit));
    }
}

// ---------------- launch ----------------
extern "C" void kernel_launch(void* const* d_in, const int* in_sizes, int n_in,
                              void* d_out, int out_size)
{
    (void)in_sizes; (void)n_in; (void)out_size;
    const float* hidden  = (const float*)d_in[0];
    const float* in_w    = (const float*)d_in[1];
    const float* in_b    = (const float*)d_in[2];
    const float* out_w   = (const float*)d_in[3];
    const float* out_b   = (const float*)d_in[4];
    const float* W1      = (const float*)d_in[5];
    const float* b1      = (const float*)d_in[6];
    const float* g1      = (const float*)d_in[7];
    const float* be1     = (const float*)d_in[8];
    const float* W2      = (const float*)d_in[9];
    const float* b2      = (const float*)d_in[10];
    const float* g2      = (const float*)d_in[11];
    const float* be2     = (const float*)d_in[12];
    const float* W3      = (const float*)d_in[13];
    const float* b3      = (const float*)d_in[14];
    const int*   lstarts = (const int*)d_in[15];
    const int*   llens   = (const int*)d_in[16];
    const int*   ctx     = (const int*)d_in[17];
    float* out = (float*)d_out;

    __nv_bfloat16 *hb, *wib, *wob, *qkvh, *atnh;
    float *oproj, *x, *y1, *y2;
    cudaGetSymbolAddress((void**)&hb,    g_hb);
    cudaGetSymbolAddress((void**)&wib,   g_wib);
    cudaGetSymbolAddress((void**)&wob,   g_wob);
    cudaGetSymbolAddress((void**)&qkvh,  g_qkvh);
    cudaGetSymbolAddress((void**)&atnh,  g_atnh);
    cudaGetSymbolAddress((void**)&oproj, g_oproj);
    cudaGetSymbolAddress((void**)&x,     g_x);
    cudaGetSymbolAddress((void**)&y1,    g_y1);
    cudaGetSymbolAddress((void**)&y2,    g_y2);

    const float qmul = 0.10206207261596577f * 1.4426950408889634f;  // 1/sqrt(96)*log2e
    const int attn_smem = NSTG * AST;   // 96KB dynamic

    static int attr_set = 0;
    if (!attr_set) {
        cudaFuncSetAttribute(attn_kernel,
                             cudaFuncAttributeMaxDynamicSharedMemorySize, attn_smem);
        attr_set = 1;
    }

    // 0) one-time f32->bf16 converts
    f2b_kernel<<<2048, 256>>>(hidden, hb,  (B_ * S_ * H_) / 2);
    f2b_kernel<<<1024, 256>>>(in_w,  wib, (QKV_ * H_) / 2);
    f2b_kernel<<<512,  256>>>(out_w, wob, (H_ * H_) / 2);

    // 1) QKV projection (bf16 out, Q columns pre-scaled)
    gemm_bf16_cp<<<dim3(QKV_ / 128, (B_ * S_) / 128), 256>>>(
        hb, wib, in_b, qkvh, B_ * S_, QKV_, H_, 1, qmul, H_);
    // 2) cross attention (4-stage pipeline)
    attn_kernel<<<dim3(LM_ / 128, NH_, B_), 256, attn_smem>>>(qkvh, lstarts, ctx, atnh);
    // 3) out_proj (bf16 in, f32 out)
    gemm_bf16_cp<<<dim3(H_ / 128, (B_ * LM_) / 128), 256>>>(
        atnh, wob, out_b, oproj, B_ * LM_, H_, H_, 0, 1.0f, 0);
    // 4) pooled features
    pool_kernel<<<B_ * L_, 256>>>(hidden, oproj, lstarts, llens, x);
    // 5) classifier head (tf32)
    gemm_tf32_nt<<<dim3(H_ / 128, (B_ * L_) / 128), 256>>>(x, W1, b1, y1, B_ * L_, H_, 2 * H_);
    ln_gelu_kernel<<<B_ * L_, 256>>>(y1, g1, be1, nullptr, y1);
    gemm_tf32_nt<<<dim3(H_ / 128, (B_ * L_) / 128), 256>>>(y1, W2, b2, y2, B_ * L_, H_, H_);
    ln_gelu_kernel<<<B_ * L_, 256>>>(y2, g2, be2, y1, y2);
    final_kernel<<<B_ * L_ / 4, 128>>>(y2, W3, b3, llens, out);
}

// round 13
// speedup vs baseline: 1.2754x; 1.2754x over previous
#include <cuda_runtime.h>
#include <cuda_bf16.h>
#include <math.h>
#include <stdint.h>

// ---------------- problem constants ----------------
#define B_    4
#define S_    2048
#define H_    768
#define NH_   8
#define DH_   96
#define L_    128
#define ML_   15
#define LM_   1920      // L_*ML_
#define QKV_  2304      // 3*H_

// ---------------- scratch ----------------
__device__ __nv_bfloat16 g_hb  [(size_t)B_ * S_ * H_];
__device__ __nv_bfloat16 g_wib [(size_t)QKV_ * H_];
__device__ __nv_bfloat16 g_wob [(size_t)H_ * H_];
__device__ __nv_bfloat16 g_qkvh[(size_t)B_ * S_ * QKV_];   // Q pre-scaled
__device__ __nv_bfloat16 g_atnh[(size_t)B_ * LM_ * H_];
__device__ float g_oproj[(size_t)B_ * LM_ * H_];
__device__ float g_x    [(size_t)B_ * L_ * 2 * H_];
__device__ float g_y1   [(size_t)B_ * L_ * H_];
__device__ float g_y2   [(size_t)B_ * L_ * H_];

// ---------------- helpers ----------------
__device__ __forceinline__ unsigned pk(float lo, float hi) {
    unsigned r;
    asm("cvt.rn.bf16x2.f32 %0, %1, %2;" : "=r"(r) : "f"(hi), "f"(lo));
    return r;
}
__device__ __forceinline__ unsigned bex2(unsigned x) {
    unsigned r;
    asm("ex2.approx.ftz.bf16x2 %0, %1;" : "=r"(r) : "r"(x));
    return r;
}
__device__ __forceinline__ void mma_bf16(float* d, const unsigned* a, const unsigned* b) {
    asm volatile(
        "mma.sync.aligned.m16n8k16.row.col.f32.bf16.bf16.f32 "
        "{%0,%1,%2,%3}, {%4,%5,%6,%7}, {%8,%9}, {%0,%1,%2,%3};"
        : "+f"(d[0]), "+f"(d[1]), "+f"(d[2]), "+f"(d[3])
        : "r"(a[0]), "r"(a[1]), "r"(a[2]), "r"(a[3]), "r"(b[0]), "r"(b[1]));
}
__device__ __forceinline__ void mma_tf32(float* d, const unsigned* a, const unsigned* b) {
    asm volatile(
        "mma.sync.aligned.m16n8k8.row.col.f32.tf32.tf32.f32 "
        "{%0,%1,%2,%3}, {%4,%5,%6,%7}, {%8,%9}, {%0,%1,%2,%3};"
        : "+f"(d[0]), "+f"(d[1]), "+f"(d[2]), "+f"(d[3])
        : "r"(a[0]), "r"(a[1]), "r"(a[2]), "r"(a[3]), "r"(b[0]), "r"(b[1]));
}
__device__ __forceinline__ uint32_t s2u(const void* p) {
    uint32_t a;
    asm("{ .reg .u64 t; cvta.to.shared.u64 t, %1; cvt.u32.u64 %0, t; }" : "=r"(a) : "l"(p));
    return a;
}
__device__ __forceinline__ void cpa16(uint32_t s, const void* g) {
    asm volatile("cp.async.cg.shared.global [%0], [%1], 16;" :: "r"(s), "l"(g));
}
#define CP_COMMIT() asm volatile("cp.async.commit_group;")
#define CP_WAIT2()  asm volatile("cp.async.wait_group 2;")
#define CP_WAIT1()  asm volatile("cp.async.wait_group 1;")
__device__ __forceinline__ void ldm4(uint4& d, uint32_t a) {
    asm volatile("ldmatrix.sync.aligned.m8n8.x4.shared.b16 {%0,%1,%2,%3}, [%4];"
                 : "=r"(d.x), "=r"(d.y), "=r"(d.z), "=r"(d.w) : "r"(a));
}
__device__ __forceinline__ void ldm4t(uint4& d, uint32_t a) {
    asm volatile("ldmatrix.sync.aligned.m8n8.x4.trans.shared.b16 {%0,%1,%2,%3}, [%4];"
                 : "=r"(d.x), "=r"(d.y), "=r"(d.z), "=r"(d.w) : "r"(a));
}

// ---------------- f32 -> bf16 convert ----------------
__global__ __launch_bounds__(256) void f2b_kernel(
    const float* __restrict__ src, __nv_bfloat16* __restrict__ dst, int n2)
{
    int stride = gridDim.x * blockDim.x;
    for (int i = blockIdx.x * blockDim.x + threadIdx.x; i < n2; i += stride) {
        float2 v = ((const float2*)src)[i];
        ((unsigned*)dst)[i] = pk(v.x, v.y);
    }
}

// ---------------- bf16 NT GEMM: cp.async 3-stage + ldmatrix ----------------
__global__ __launch_bounds__(256) void gemm_bf16_cp(
    const __nv_bfloat16* __restrict__ A, const __nv_bfloat16* __restrict__ Bw,
    const float* __restrict__ bias, void* __restrict__ Cout,
    int M, int N, int K, int out_bf16, float qmul, int qcols)
{
    __shared__ __align__(16) char smem[3 * 16384];

    int tid = threadIdx.x;
    int warp = tid >> 5, lane = tid & 31;
    int warp_m = warp >> 1, warp_n = warp & 1;
    int m0 = blockIdx.y * 128, n0 = blockIdx.x * 128;
    uint32_t sbase = s2u(smem);

    float acc[2][8][4];
#pragma unroll
    for (int mi = 0; mi < 2; mi++)
#pragma unroll
        for (int ni = 0; ni < 8; ni++)
#pragma unroll
            for (int r = 0; r < 4; r++) acc[mi][ni][r] = 0.0f;

    int nslab = K >> 5;
    int frow0 = tid >> 2,        fc0 = tid & 3;
    int frow1 = (tid + 256) >> 2, fc1 = (tid + 256) & 3;

#define FILL(st, sl)                                                                   \
    do {                                                                               \
        int k0f = (sl) << 5;                                                           \
        uint32_t sa = sbase + (st) * 16384;                                            \
        uint32_t sb = sa + 8192;                                                       \
        cpa16(sa + (frow0 * 4 + (fc0 ^ ((frow0 >> 1) & 3))) * 16,                      \
              A + (size_t)(m0 + frow0) * K + k0f + fc0 * 8);                           \
        cpa16(sa + (frow1 * 4 + (fc1 ^ ((frow1 >> 1) & 3))) * 16,                      \
              A + (size_t)(m0 + frow1) * K + k0f + fc1 * 8);                           \
        cpa16(sb + (frow0 * 4 + (fc0 ^ ((frow0 >> 1) & 3))) * 16,                      \
              Bw + (size_t)(n0 + frow0) * K + k0f + fc0 * 8);                          \
        cpa16(sb + (frow1 * 4 + (fc1 ^ ((frow1 >> 1) & 3))) * 16,                      \
              Bw + (size_t)(n0 + frow1) * K + k0f + fc1 * 8);                          \
    } while (0)

    FILL(0, 0); CP_COMMIT();
    if (nslab > 1) FILL(1, 1);
    CP_COMMIT();

    for (int i = 0; i < nslab; i++) {
        if (i + 2 < nslab) FILL((i + 2) % 3, i + 2);
        CP_COMMIT();
        CP_WAIT2();
        __syncthreads();

        uint32_t sa = sbase + (i % 3) * 16384;
        uint32_t sb = sa + 8192;
#pragma unroll
        for (int ks = 0; ks < 2; ks++) {
            uint4 afr[2];
#pragma unroll
            for (int mi = 0; mi < 2; mi++) {
                int row = warp_m * 32 + mi * 16 + ((lane >> 3) & 1) * 8 + (lane & 7);
                int ch = ks * 2 + (lane >> 4);
                ldm4(afr[mi], sa + (row * 4 + (ch ^ ((row >> 1) & 3))) * 16);
            }
            uint4 bfr[4];
#pragma unroll
            for (int nj = 0; nj < 4; nj++) {
                int row = warp_n * 64 + nj * 16 + ((lane >> 4) & 1) * 8 + (lane & 7);
                int ch = ks * 2 + ((lane >> 3) & 1);
                ldm4(bfr[nj], sb + (row * 4 + (ch ^ ((row >> 1) & 3))) * 16);
            }
#pragma unroll
            for (int mi = 0; mi < 2; mi++)
#pragma unroll
                for (int nj = 0; nj < 4; nj++) {
                    mma_bf16(acc[mi][2 * nj],     (const unsigned*)&afr[mi], &bfr[nj].x);
                    mma_bf16(acc[mi][2 * nj + 1], (const unsigned*)&afr[mi], &bfr[nj].z);
                }
        }
        __syncthreads();
    }
#undef FILL

#pragma unroll
    for (int mi = 0; mi < 2; mi++) {
        int row = m0 + warp_m * 32 + mi * 16 + (lane >> 2);
#pragma unroll
        for (int ni = 0; ni < 8; ni++) {
            int col = n0 + warp_n * 64 + ni * 8 + ((lane & 3) << 1);
            float b0 = bias ? bias[col] : 0.0f;
            float b1 = bias ? bias[col + 1] : 0.0f;
            float v0 = acc[mi][ni][0] + b0, v1 = acc[mi][ni][1] + b1;
            float v2 = acc[mi][ni][2] + b0, v3 = acc[mi][ni][3] + b1;
            if (out_bf16) {
                float s = (col < qcols) ? qmul : 1.0f;
                __nv_bfloat16* Cb = (__nv_bfloat16*)Cout;
                *(unsigned*)(Cb + (size_t)row * N + col)       = pk(v0 * s, v1 * s);
                *(unsigned*)(Cb + (size_t)(row + 8) * N + col) = pk(v2 * s, v3 * s);
            } else {
                float* Cf = (float*)Cout;
                *(float2*)(Cf + (size_t)row * N + col)       = make_float2(v0, v1);
                *(float2*)(Cf + (size_t)(row + 8) * N + col) = make_float2(v2, v3);
            }
        }
    }
}

// ---------------- tf32 NT GEMM with split-K (classifier) ----------------
// grid.z partitions K into Kper-sized ranges; partials combined via atomicAdd.
// C must be zero-initialized. Bias added by z==0 only.
__global__ __launch_bounds__(256) void gemm_tf32_sk(
    const float* __restrict__ A, const float* __restrict__ Bw,
    const float* __restrict__ bias, float* __restrict__ C,
    int M, int N, int K, int Kper)
{
    __shared__ unsigned As[4 * 8 * 128];
    __shared__ unsigned Bs[4 * 16 * 64];

    int tid = threadIdx.x;
    int warp = tid >> 5, lane = tid & 31;
    int warp_m = warp >> 1, warp_n = warp & 1;
    int m0 = blockIdx.y * 128, n0 = blockIdx.x * 128;
    int kz0 = blockIdx.z * Kper;

    float acc[2][8][4];
#pragma unroll
    for (int mi = 0; mi < 2; mi++)
#pragma unroll
        for (int ni = 0; ni < 8; ni++)
#pragma unroll
            for (int r = 0; r < 4; r++) acc[mi][ni][r] = 0.0f;

    for (int k0 = kz0; k0 < kz0 + Kper; k0 += 32) {
        __syncthreads();
#pragma unroll
        for (int i = 0; i < 4; i++) {
            int f = tid + i * 256;
            int row = f >> 3, kq = f & 7;
            float4 v = *(const float4*)(A + (size_t)(m0 + row) * K + k0 + kq * 4);
            int mtile = row >> 4, r = row & 15, ktile = kq >> 1;
            int regb = (r >> 3) + ((kq & 1) << 1);
            unsigned* p = &As[((ktile * 8 + mtile) * 32 + (r & 7) * 4) * 4 + regb];
            p[0]  = __float_as_uint(v.x);
            p[4]  = __float_as_uint(v.y);
            p[8]  = __float_as_uint(v.z);
            p[12] = __float_as_uint(v.w);
        }
#pragma unroll
        for (int i = 0; i < 4; i++) {
            int f = tid + i * 256;
            int row = f >> 3, kq = f & 7;
            float4 v = *(const float4*)(Bw + (size_t)(n0 + row) * K + k0 + kq * 4);
            int ntile = row >> 3, ktile = kq >> 1, reg = kq & 1;
            unsigned* p = &Bs[(ktile * 16 + ntile) * 64 + (row & 7) * 8 + reg];
            p[0] = __float_as_uint(v.x);
            p[2] = __float_as_uint(v.y);
            p[4] = __float_as_uint(v.z);
            p[6] = __float_as_uint(v.w);
        }
        __syncthreads();
#pragma unroll
        for (int ks = 0; ks < 4; ks++) {
            uint4 a[2];
            uint2 b[8];
#pragma unroll
            for (int mi = 0; mi < 2; mi++)
                a[mi] = *(const uint4*)&As[((ks * 8 + warp_m * 2 + mi) * 32 + lane) * 4];
#pragma unroll
            for (int ni = 0; ni < 8; ni++)
                b[ni] = *(const uint2*)&Bs[((ks * 16 + warp_n * 8 + ni) * 32 + lane) * 2];
#pragma unroll
            for (int mi = 0; mi < 2; mi++)
#pragma unroll
                for (int ni = 0; ni < 8; ni++)
                    mma_tf32(acc[mi][ni], (const unsigned*)&a[mi], (const unsigned*)&b[ni]);
        }
    }

    int add_bias = (bias != nullptr) && (blockIdx.z == 0);
#pragma unroll
    for (int mi = 0; mi < 2; mi++) {
        int row = m0 + warp_m * 32 + mi * 16 + (lane >> 2);
#pragma unroll
        for (int ni = 0; ni < 8; ni++) {
            int col = n0 + warp_n * 64 + ni * 8 + ((lane & 3) << 1);
            float b0 = add_bias ? bias[col] : 0.0f;
            float b1 = add_bias ? bias[col + 1] : 0.0f;
            atomicAdd(&C[(size_t)row * N + col],           acc[mi][ni][0] + b0);
            atomicAdd(&C[(size_t)row * N + col + 1],       acc[mi][ni][1] + b1);
            atomicAdd(&C[(size_t)(row + 8) * N + col],     acc[mi][ni][2] + b0);
            atomicAdd(&C[(size_t)(row + 8) * N + col + 1], acc[mi][ni][3] + b1);
        }
    }
}

// ---------------- bf16 flash cross-attention: 2-stage pipeline (round-11 best) ----------------
#define AST 24576   // per-stage: K 12288 + V 12288
__global__ __launch_bounds__(256, 2) void attn_kernel(
    const __nv_bfloat16* __restrict__ qkv,
    const int* __restrict__ line_starts,
    const int* __restrict__ ctx_len,
    __nv_bfloat16* __restrict__ out)
{
    __shared__ __align__(16) char smem[2 * AST];   // 48KB

    int tid = threadIdx.x;
    int warp = tid >> 5, lane = tid & 31;
    int b = blockIdx.z, h = blockIdx.y, q0 = blockIdx.x * 128;
    uint32_t sb = s2u(smem);

    int r0 = warp * 16 + (lane >> 2);
    int c2 = (lane & 3) * 2;
    int ctx = ctx_len[b];

    const __nv_bfloat16 *qp0, *qp1;
    {
        int gq0 = q0 + r0;
        int l0i = gq0 / ML_, mm0 = gq0 - l0i * ML_;
        int pos0 = min(max(line_starts[b * L_ + l0i] + mm0, 0), S_ - 1);
        int gq1 = gq0 + 8;
        int l1i = gq1 / ML_, mm1 = gq1 - l1i * ML_;
        int pos1 = min(max(line_starts[b * L_ + l1i] + mm1, 0), S_ - 1);
        qp0 = qkv + ((size_t)b * S_ + pos0) * QKV_ + h * DH_;
        qp1 = qkv + ((size_t)b * S_ + pos1) * QKV_ + h * DH_;
    }
    unsigned qf[6][4];
#pragma unroll
    for (int ks = 0; ks < 6; ks++) {
        qf[ks][0] = *(const unsigned*)(qp0 + ks * 16 + c2);
        qf[ks][1] = *(const unsigned*)(qp1 + ks * 16 + c2);
        qf[ks][2] = *(const unsigned*)(qp0 + ks * 16 + c2 + 8);
        qf[ks][3] = *(const unsigned*)(qp1 + ks * 16 + c2 + 8);
    }

    const __nv_bfloat16 *kg[3], *vg[3];
    int foff[3];
#pragma unroll
    for (int i = 0; i < 3; i++) {
        int u = tid + i * 256;
        int row = u / 12, c = u - row * 12;
        foff[i] = row * 192 + (c ^ ((row >> 1) & 3)) * 16;
        kg[i] = qkv + ((size_t)b * S_ + row) * QKV_ + H_ + h * DH_ + c * 8;
        vg[i] = kg[i] + H_;
    }

    int sm = lane >> 3;
    int srow = (sm >> 1) * 8 + (lane & 7);
    int scb = sm & 1;
    int sprow[4], spsw[4];
#pragma unroll
    for (int np = 0; np < 4; np++) {
        int row = np * 16 + srow;
        sprow[np] = row * 192;
        spsw[np] = (row >> 1) & 3;
    }
    int vrow_b = (sm & 1) * 8 + (lane & 7);
    int vcb = sm >> 1;
    int vprow[4], vpsw[4];
#pragma unroll
    for (int ks = 0; ks < 4; ks++) {
        int row = ks * 16 + vrow_b;
        vprow[ks] = row * 192;
        vpsw[ks] = (row >> 1) & 3;
    }

    const unsigned bones[2] = {0x3F803F80u, 0x3F803F80u};

    float Oacc[12][4], lacc[4];
#pragma unroll
    for (int nt = 0; nt < 12; nt++)
#pragma unroll
        for (int r = 0; r < 4; r++) Oacc[nt][r] = 0.0f;
#pragma unroll
    for (int r = 0; r < 4; r++) lacc[r] = 0.0f;

#define AFILL(st, s0f)                                                          \
    do {                                                                        \
        uint32_t kb_ = sb + (st) * AST;                                         \
        uint32_t vb_ = kb_ + 12288;                                             \
        _Pragma("unroll")                                                       \
        for (int i_ = 0; i_ < 3; i_++) {                                        \
            cpa16(kb_ + foff[i_], kg[i_] + (size_t)(s0f) * QKV_);               \
            cpa16(vb_ + foff[i_], vg[i_] + (size_t)(s0f) * QKV_);               \
        }                                                                       \
    } while (0)

    AFILL(0, 0); CP_COMMIT();

    for (int ci = 0; ci < 32; ci++) {
        int s0 = ci * 64;
        if (ci < 31) AFILL((ci + 1) & 1, s0 + 64);
        CP_COMMIT();
        CP_WAIT1();
        __syncthreads();

        uint32_t Kst = sb + (ci & 1) * AST;
        uint32_t Vst = Kst + 12288;

        float sacc[8][4];
#pragma unroll
        for (int nt = 0; nt < 8; nt++)
#pragma unroll
            for (int r = 0; r < 4; r++) sacc[nt][r] = 0.0f;
#pragma unroll
        for (int ks = 0; ks < 6; ks++) {
#pragma unroll
            for (int np = 0; np < 4; np++) {
                uint4 kb;
                ldm4(kb, Kst + sprow[np] + ((2 * ks + scb) ^ spsw[np]) * 16);
                mma_bf16(sacc[2 * np],     qf[ks], &kb.x);
                mma_bf16(sacc[2 * np + 1], qf[ks], &kb.z);
            }
        }

        if (s0 + 64 > ctx) {
#pragma unroll
            for (int nt = 0; nt < 8; nt++) {
                int t = s0 + nt * 8 + c2;
                if (t >= ctx)     { sacc[nt][0] = -3e38f; sacc[nt][2] = -3e38f; }
                if (t + 1 >= ctx) { sacc[nt][1] = -3e38f; sacc[nt][3] = -3e38f; }
            }
        }

#pragma unroll
        for (int ks = 0; ks < 4; ks++) {
            unsigned pa[4];
            pa[0] = bex2(pk(sacc[2 * ks][0],     sacc[2 * ks][1]));
            pa[1] = bex2(pk(sacc[2 * ks][2],     sacc[2 * ks][3]));
            pa[2] = bex2(pk(sacc[2 * ks + 1][0], sacc[2 * ks + 1][1]));
            pa[3] = bex2(pk(sacc[2 * ks + 1][2], sacc[2 * ks + 1][3]));
            mma_bf16(lacc, pa, bones);
#pragma unroll
            for (int np = 0; np < 6; np++) {
                uint4 vb;
                ldm4t(vb, Vst + vprow[ks] + ((2 * np + vcb) ^ vpsw[ks]) * 16);
                mma_bf16(Oacc[2 * np],     pa, &vb.x);
                mma_bf16(Oacc[2 * np + 1], pa, &vb.z);
            }
        }
        __syncthreads();
    }
#undef AFILL

    float inv0 = 1.0f / lacc[0];
    float inv1 = 1.0f / lacc[2];
#pragma unroll
    for (int nt = 0; nt < 12; nt++) {
        int col = h * DH_ + nt * 8 + c2;
        *(unsigned*)(out + ((size_t)b * LM_ + q0 + r0) * H_ + col) =
            pk(Oacc[nt][0] * inv0, Oacc[nt][1] * inv0);
        *(unsigned*)(out + ((size_t)b * LM_ + q0 + r0 + 8) * H_ + col) =
            pk(Oacc[nt][2] * inv1, Oacc[nt][3] * inv1);
    }
}

// ---------------- masked mean-pool ----------------
__global__ __launch_bounds__(256) void pool_kernel(
    const float* __restrict__ hidden, const float* __restrict__ oproj,
    const int* __restrict__ line_starts, const int* __restrict__ line_lens,
    float* __restrict__ x)
{
    int bl = blockIdx.x;
    int b = bl / L_;
    int len = line_lens[bl];
    int start = line_starts[bl];
    float inv = 1.0f / (float)max(len, 1);
    for (int c = threadIdx.x; c < H_; c += 256) {
        float s1 = 0.0f, s2 = 0.0f;
        for (int m = 0; m < ML_; m++) {
            if (m < len) {
                int pos = min(max(start + m, 0), S_ - 1);
                s1 += hidden[((size_t)b * S_ + pos) * H_ + c];
                s2 += oproj[((size_t)bl * ML_ + m) * H_ + c];
            }
        }
        x[(size_t)bl * 2 * H_ + c]      = s1 * inv;
        x[(size_t)bl * 2 * H_ + H_ + c] = s2 * inv;
    }
}

// ---------------- LayerNorm -> exact GELU (+optional residual) ----------------
__global__ __launch_bounds__(256) void ln_gelu_kernel(
    const float* __restrict__ y, const float* __restrict__ g,
    const float* __restrict__ be, const float* __restrict__ res,
    float* __restrict__ out)
{
    __shared__ float red1[8], red2[8];
    int row = blockIdx.x;
    const float* yr = y + (size_t)row * H_;
    float v[3], sum = 0.0f, sq = 0.0f;
#pragma unroll
    for (int i = 0; i < 3; i++) {
        v[i] = yr[threadIdx.x + 256 * i];
        sum += v[i];
        sq  += v[i] * v[i];
    }
#pragma unroll
    for (int o = 16; o > 0; o >>= 1) {
        sum += __shfl_xor_sync(0xffffffffu, sum, o);
        sq  += __shfl_xor_sync(0xffffffffu, sq,  o);
    }
    int warp = threadIdx.x >> 5;
    if ((threadIdx.x & 31) == 0) { red1[warp] = sum; red2[warp] = sq; }
    __syncthreads();
    float tsum = 0.0f, tsq = 0.0f;
#pragma unroll
    for (int i = 0; i < 8; i++) { tsum += red1[i]; tsq += red2[i]; }
    float mean = tsum * (1.0f / H_);
    float var  = tsq  * (1.0f / H_) - mean * mean;
    float rstd = rsqrtf(var + 1e-5f);
#pragma unroll
    for (int i = 0; i < 3; i++) {
        int c = threadIdx.x + 256 * i;
        float t  = (v[i] - mean) * rstd * g[c] + be[c];
        float ge = 0.5f * t * (1.0f + erff(t * 0.70710678118654752f));
        out[(size_t)row * H_ + c] = (res ? res[(size_t)row * H_ + c] : 0.0f) + ge;
    }
}

// ---------------- final logit ----------------
__global__ __launch_bounds__(128) void final_kernel(
    const float* __restrict__ a2, const float* __restrict__ W3,
    const float* __restrict__ b3, const int* __restrict__ line_lens,
    float* __restrict__ out)
{
    int row  = blockIdx.x * 4 + (threadIdx.x >> 5);
    int lane = threadIdx.x & 31;
    float s = 0.0f;
    for (int c = lane; c < H_; c += 32)
        s += a2[(size_t)row * H_ + c] * W3[c];
#pragma unroll
    for (int o = 16; o > 0; o >>= 1) s += __shfl_xor_sync(0xffffffffu, s, o);
    if (lane == 0) {
        float logit = s + b3[0];
        if (line_lens[row] <= 0) logit = -10.0f;
        out[row] = 1.0f / (1.0f + __expf(-logit));
    }
}

// ---------------- launch ----------------
extern "C" void kernel_launch(void* const* d_in, const int* in_sizes, int n_in,
                              void* d_out, int out_size)
{
    (void)in_sizes; (void)n_in; (void)out_size;
    const float* hidden  = (const float*)d_in[0];
    const float* in_w    = (const float*)d_in[1];
    const float* in_b    = (const float*)d_in[2];
    const float* out_w   = (const float*)d_in[3];
    const float* out_b   = (const float*)d_in[4];
    const float* W1      = (const float*)d_in[5];
    const float* b1      = (const float*)d_in[6];
    const float* g1      = (const float*)d_in[7];
    const float* be1     = (const float*)d_in[8];
    const float* W2      = (const float*)d_in[9];
    const float* b2      = (const float*)d_in[10];
    const float* g2      = (const float*)d_in[11];
    const float* be2     = (const float*)d_in[12];
    const float* W3      = (const float*)d_in[13];
    const float* b3      = (const float*)d_in[14];
    const int*   lstarts = (const int*)d_in[15];
    const int*   llens   = (const int*)d_in[16];
    const int*   ctx     = (const int*)d_in[17];
    float* out = (float*)d_out;

    __nv_bfloat16 *hb, *wib, *wob, *qkvh, *atnh;
    float *oproj, *x, *y1, *y2;
    cudaGetSymbolAddress((void**)&hb,    g_hb);
    cudaGetSymbolAddress((void**)&wib,   g_wib);
    cudaGetSymbolAddress((void**)&wob,   g_wob);
    cudaGetSymbolAddress((void**)&qkvh,  g_qkvh);
    cudaGetSymbolAddress((void**)&atnh,  g_atnh);
    cudaGetSymbolAddress((void**)&oproj, g_oproj);
    cudaGetSymbolAddress((void**)&x,     g_x);
    cudaGetSymbolAddress((void**)&y1,    g_y1);
    cudaGetSymbolAddress((void**)&y2,    g_y2);

    const float qmul = 0.10206207261596577f * 1.4426950408889634f;  // 1/sqrt(96)*log2e

    // 0) one-time f32->bf16 converts + zero split-K outputs
    f2b_kernel<<<2048, 256>>>(hidden, hb,  (B_ * S_ * H_) / 2);
    f2b_kernel<<<1024, 256>>>(in_w,  wib, (QKV_ * H_) / 2);
    f2b_kernel<<<512,  256>>>(out_w, wob, (H_ * H_) / 2);
    cudaMemsetAsync(y1, 0, (size_t)B_ * L_ * H_ * sizeof(float));
    cudaMemsetAsync(y2, 0, (size_t)B_ * L_ * H_ * sizeof(float));

    // 1) QKV projection (bf16 out, Q columns pre-scaled)
    gemm_bf16_cp<<<dim3(QKV_ / 128, (B_ * S_) / 128), 256>>>(
        hb, wib, in_b, qkvh, B_ * S_, QKV_, H_, 1, qmul, H_);
    // 2) cross attention
    attn_kernel<<<dim3(LM_ / 128, NH_, B_), 256>>>(qkvh, lstarts, ctx, atnh);
    // 3) out_proj (bf16 in, f32 out)
    gemm_bf16_cp<<<dim3(H_ / 128, (B_ * LM_) / 128), 256>>>(
        atnh, wob, out_b, oproj, B_ * LM_, H_, H_, 0, 1.0f, 0);
    // 4) pooled features
    pool_kernel<<<B_ * L_, 256>>>(hidden, oproj, lstarts, llens, x);
    // 5) classifier head (tf32, split-K x4 -> 96 CTAs per GEMM)
    gemm_tf32_sk<<<dim3(H_ / 128, (B_ * L_) / 128, 4), 256>>>(
        x, W1, b1, y1, B_ * L_, H_, 2 * H_, 2 * H_ / 4);
    ln_gelu_kernel<<<B_ * L_, 256>>>(y1, g1, be1, nullptr, y1);
    gemm_tf32_sk<<<dim3(H_ / 128, (B_ * L_) / 128, 4), 256>>>(
        y1, W2, b2, y2, B_ * L_, H_, H_, H_ / 4);
    ln_gelu_kernel<<<B_ * L_, 256>>>(y2, g2, be2, y1, y2);
    final_kernel<<<B_ * L_ / 4, 128>>>(y2, W3, b3, llens, out);
}

// round 15
// speedup vs baseline: 1.2789x; 1.0027x over previous
#include <cuda_runtime.h>
#include <cuda_bf16.h>
#include <math.h>
#include <stdint.h>

// ---------------- problem constants ----------------
#define B_    4
#define S_    2048
#define H_    768
#define NH_   8
#define DH_   96
#define L_    128
#define ML_   15
#define LM_   1920      // L_*ML_
#define QKV_  2304      // 3*H_

// ---------------- scratch ----------------
__device__ __nv_bfloat16 g_hb  [(size_t)B_ * S_ * H_];
__device__ __nv_bfloat16 g_wib [(size_t)QKV_ * H_];
__device__ __nv_bfloat16 g_wob [(size_t)H_ * H_];
__device__ __nv_bfloat16 g_qkvh[(size_t)B_ * S_ * QKV_];   // Q pre-scaled
__device__ __nv_bfloat16 g_atnh[(size_t)B_ * LM_ * H_];
__device__ float g_oproj[(size_t)B_ * LM_ * H_];
__device__ float g_x    [(size_t)B_ * L_ * 2 * H_];
__device__ float g_y1   [(size_t)B_ * L_ * H_];
__device__ float g_y2   [(size_t)B_ * L_ * H_];

// ---------------- helpers ----------------
__device__ __forceinline__ unsigned pk(float lo, float hi) {
    unsigned r;
    asm("cvt.rn.bf16x2.f32 %0, %1, %2;" : "=r"(r) : "f"(hi), "f"(lo));
    return r;
}
__device__ __forceinline__ unsigned bex2(unsigned x) {
    unsigned r;
    asm("ex2.approx.ftz.bf16x2 %0, %1;" : "=r"(r) : "r"(x));
    return r;
}
__device__ __forceinline__ void mma_bf16(float* d, const unsigned* a, const unsigned* b) {
    asm volatile(
        "mma.sync.aligned.m16n8k16.row.col.f32.bf16.bf16.f32 "
        "{%0,%1,%2,%3}, {%4,%5,%6,%7}, {%8,%9}, {%0,%1,%2,%3};"
        : "+f"(d[0]), "+f"(d[1]), "+f"(d[2]), "+f"(d[3])
        : "r"(a[0]), "r"(a[1]), "r"(a[2]), "r"(a[3]), "r"(b[0]), "r"(b[1]));
}
__device__ __forceinline__ void mma_tf32(float* d, const unsigned* a, const unsigned* b) {
    asm volatile(
        "mma.sync.aligned.m16n8k8.row.col.f32.tf32.tf32.f32 "
        "{%0,%1,%2,%3}, {%4,%5,%6,%7}, {%8,%9}, {%0,%1,%2,%3};"
        : "+f"(d[0]), "+f"(d[1]), "+f"(d[2]), "+f"(d[3])
        : "r"(a[0]), "r"(a[1]), "r"(a[2]), "r"(a[3]), "r"(b[0]), "r"(b[1]));
}
__device__ __forceinline__ uint32_t s2u(const void* p) {
    uint32_t a;
    asm("{ .reg .u64 t; cvta.to.shared.u64 t, %1; cvt.u32.u64 %0, t; }" : "=r"(a) : "l"(p));
    return a;
}
__device__ __forceinline__ void cpa16(uint32_t s, const void* g) {
    asm volatile("cp.async.cg.shared.global [%0], [%1], 16;" :: "r"(s), "l"(g));
}
#define CP_COMMIT() asm volatile("cp.async.commit_group;")
#define CP_WAIT2()  asm volatile("cp.async.wait_group 2;")
#define CP_WAIT1()  asm volatile("cp.async.wait_group 1;")
__device__ __forceinline__ void ldm4(uint4& d, uint32_t a) {
    asm volatile("ldmatrix.sync.aligned.m8n8.x4.shared.b16 {%0,%1,%2,%3}, [%4];"
                 : "=r"(d.x), "=r"(d.y), "=r"(d.z), "=r"(d.w) : "r"(a));
}
__device__ __forceinline__ void ldm4t(uint4& d, uint32_t a) {
    asm volatile("ldmatrix.sync.aligned.m8n8.x4.trans.shared.b16 {%0,%1,%2,%3}, [%4];"
                 : "=r"(d.x), "=r"(d.y), "=r"(d.z), "=r"(d.w) : "r"(a));
}

// ---------------- f32 -> bf16 convert ----------------
__global__ __launch_bounds__(256) void f2b_kernel(
    const float* __restrict__ src, __nv_bfloat16* __restrict__ dst, int n2)
{
    int stride = gridDim.x * blockDim.x;
    for (int i = blockIdx.x * blockDim.x + threadIdx.x; i < n2; i += stride) {
        float2 v = ((const float2*)src)[i];
        ((unsigned*)dst)[i] = pk(v.x, v.y);
    }
}

// ---------------- bf16 NT GEMM: cp.async 3-stage + ldmatrix ----------------
__global__ __launch_bounds__(256, 2) void gemm_bf16_cp(
    const __nv_bfloat16* __restrict__ A, const __nv_bfloat16* __restrict__ Bw,
    const float* __restrict__ bias, void* __restrict__ Cout,
    int M, int N, int K, int out_bf16, float qmul, int qcols)
{
    __shared__ __align__(16) char smem[3 * 16384];

    int tid = threadIdx.x;
    int warp = tid >> 5, lane = tid & 31;
    int warp_m = warp >> 1, warp_n = warp & 1;
    int m0 = blockIdx.y * 128, n0 = blockIdx.x * 128;
    uint32_t sbase = s2u(smem);

    float acc[2][8][4];
#pragma unroll
    for (int mi = 0; mi < 2; mi++)
#pragma unroll
        for (int ni = 0; ni < 8; ni++)
#pragma unroll
            for (int r = 0; r < 4; r++) acc[mi][ni][r] = 0.0f;

    int nslab = K >> 5;
    int frow0 = tid >> 2,        fc0 = tid & 3;
    int frow1 = (tid + 256) >> 2, fc1 = (tid + 256) & 3;

#define FILL(st, sl)                                                                   \
    do {                                                                               \
        int k0f = (sl) << 5;                                                           \
        uint32_t sa = sbase + (st) * 16384;                                            \
        uint32_t sb = sa + 8192;                                                       \
        cpa16(sa + (frow0 * 4 + (fc0 ^ ((frow0 >> 1) & 3))) * 16,                      \
              A + (size_t)(m0 + frow0) * K + k0f + fc0 * 8);                           \
        cpa16(sa + (frow1 * 4 + (fc1 ^ ((frow1 >> 1) & 3))) * 16,                      \
              A + (size_t)(m0 + frow1) * K + k0f + fc1 * 8);                           \
        cpa16(sb + (frow0 * 4 + (fc0 ^ ((frow0 >> 1) & 3))) * 16,                      \
              Bw + (size_t)(n0 + frow0) * K + k0f + fc0 * 8);                          \
        cpa16(sb + (frow1 * 4 + (fc1 ^ ((frow1 >> 1) & 3))) * 16,                      \
              Bw + (size_t)(n0 + frow1) * K + k0f + fc1 * 8);                          \
    } while (0)

    FILL(0, 0); CP_COMMIT();
    if (nslab > 1) FILL(1, 1);
    CP_COMMIT();

    for (int i = 0; i < nslab; i++) {
        if (i + 2 < nslab) FILL((i + 2) % 3, i + 2);
        CP_COMMIT();
        CP_WAIT2();
        __syncthreads();

        uint32_t sa = sbase + (i % 3) * 16384;
        uint32_t sb = sa + 8192;
#pragma unroll
        for (int ks = 0; ks < 2; ks++) {
            uint4 afr[2];
#pragma unroll
            for (int mi = 0; mi < 2; mi++) {
                int row = warp_m * 32 + mi * 16 + ((lane >> 3) & 1) * 8 + (lane & 7);
                int ch = ks * 2 + (lane >> 4);
                ldm4(afr[mi], sa + (row * 4 + (ch ^ ((row >> 1) & 3))) * 16);
            }
            uint4 bfr[4];
#pragma unroll
            for (int nj = 0; nj < 4; nj++) {
                int row = warp_n * 64 + nj * 16 + ((lane >> 4) & 1) * 8 + (lane & 7);
                int ch = ks * 2 + ((lane >> 3) & 1);
                ldm4(bfr[nj], sb + (row * 4 + (ch ^ ((row >> 1) & 3))) * 16);
            }
#pragma unroll
            for (int mi = 0; mi < 2; mi++)
#pragma unroll
                for (int nj = 0; nj < 4; nj++) {
                    mma_bf16(acc[mi][2 * nj],     (const unsigned*)&afr[mi], &bfr[nj].x);
                    mma_bf16(acc[mi][2 * nj + 1], (const unsigned*)&afr[mi], &bfr[nj].z);
                }
        }
        __syncthreads();
    }
#undef FILL

#pragma unroll
    for (int mi = 0; mi < 2; mi++) {
        int row = m0 + warp_m * 32 + mi * 16 + (lane >> 2);
#pragma unroll
        for (int ni = 0; ni < 8; ni++) {
            int col = n0 + warp_n * 64 + ni * 8 + ((lane & 3) << 1);
            float b0 = bias ? bias[col] : 0.0f;
            float b1 = bias ? bias[col + 1] : 0.0f;
            float v0 = acc[mi][ni][0] + b0, v1 = acc[mi][ni][1] + b1;
            float v2 = acc[mi][ni][2] + b0, v3 = acc[mi][ni][3] + b1;
            if (out_bf16) {
                float s = (col < qcols) ? qmul : 1.0f;
                __nv_bfloat16* Cb = (__nv_bfloat16*)Cout;
                *(unsigned*)(Cb + (size_t)row * N + col)       = pk(v0 * s, v1 * s);
                *(unsigned*)(Cb + (size_t)(row + 8) * N + col) = pk(v2 * s, v3 * s);
            } else {
                float* Cf = (float*)Cout;
                *(float2*)(Cf + (size_t)row * N + col)       = make_float2(v0, v1);
                *(float2*)(Cf + (size_t)(row + 8) * N + col) = make_float2(v2, v3);
            }
        }
    }
}

// ---------------- tf32 NT GEMM with split-K (classifier) ----------------
__global__ __launch_bounds__(256) void gemm_tf32_sk(
    const float* __restrict__ A, const float* __restrict__ Bw,
    const float* __restrict__ bias, float* __restrict__ C,
    int M, int N, int K, int Kper)
{
    __shared__ unsigned As[4 * 8 * 128];
    __shared__ unsigned Bs[4 * 16 * 64];

    int tid = threadIdx.x;
    int warp = tid >> 5, lane = tid & 31;
    int warp_m = warp >> 1, warp_n = warp & 1;
    int m0 = blockIdx.y * 128, n0 = blockIdx.x * 128;
    int kz0 = blockIdx.z * Kper;

    float acc[2][8][4];
#pragma unroll
    for (int mi = 0; mi < 2; mi++)
#pragma unroll
        for (int ni = 0; ni < 8; ni++)
#pragma unroll
            for (int r = 0; r < 4; r++) acc[mi][ni][r] = 0.0f;

    for (int k0 = kz0; k0 < kz0 + Kper; k0 += 32) {
        __syncthreads();
#pragma unroll
        for (int i = 0; i < 4; i++) {
            int f = tid + i * 256;
            int row = f >> 3, kq = f & 7;
            float4 v = *(const float4*)(A + (size_t)(m0 + row) * K + k0 + kq * 4);
            int mtile = row >> 4, r = row & 15, ktile = kq >> 1;
            int regb = (r >> 3) + ((kq & 1) << 1);
            unsigned* p = &As[((ktile * 8 + mtile) * 32 + (r & 7) * 4) * 4 + regb];
            p[0]  = __float_as_uint(v.x);
            p[4]  = __float_as_uint(v.y);
            p[8]  = __float_as_uint(v.z);
            p[12] = __float_as_uint(v.w);
        }
#pragma unroll
        for (int i = 0; i < 4; i++) {
            int f = tid + i * 256;
            int row = f >> 3, kq = f & 7;
            float4 v = *(const float4*)(Bw + (size_t)(n0 + row) * K + k0 + kq * 4);
            int ntile = row >> 3, ktile = kq >> 1, reg = kq & 1;
            unsigned* p = &Bs[(ktile * 16 + ntile) * 64 + (row & 7) * 8 + reg];
            p[0] = __float_as_uint(v.x);
            p[2] = __float_as_uint(v.y);
            p[4] = __float_as_uint(v.z);
            p[6] = __float_as_uint(v.w);
        }
        __syncthreads();
#pragma unroll
        for (int ks = 0; ks < 4; ks++) {
            uint4 a[2];
            uint2 b[8];
#pragma unroll
            for (int mi = 0; mi < 2; mi++)
                a[mi] = *(const uint4*)&As[((ks * 8 + warp_m * 2 + mi) * 32 + lane) * 4];
#pragma unroll
            for (int ni = 0; ni < 8; ni++)
                b[ni] = *(const uint2*)&Bs[((ks * 16 + warp_n * 8 + ni) * 32 + lane) * 2];
#pragma unroll
            for (int mi = 0; mi < 2; mi++)
#pragma unroll
                for (int ni = 0; ni < 8; ni++)
                    mma_tf32(acc[mi][ni], (const unsigned*)&a[mi], (const unsigned*)&b[ni]);
        }
    }

    int add_bias = (bias != nullptr) && (blockIdx.z == 0);
#pragma unroll
    for (int mi = 0; mi < 2; mi++) {
        int row = m0 + warp_m * 32 + mi * 16 + (lane >> 2);
#pragma unroll
        for (int ni = 0; ni < 8; ni++) {
            int col = n0 + warp_n * 64 + ni * 8 + ((lane & 3) << 1);
            float b0 = add_bias ? bias[col] : 0.0f;
            float b1 = add_bias ? bias[col + 1] : 0.0f;
            atomicAdd(&C[(size_t)row * N + col],           acc[mi][ni][0] + b0);
            atomicAdd(&C[(size_t)row * N + col + 1],       acc[mi][ni][1] + b1);
            atomicAdd(&C[(size_t)(row + 8) * N + col],     acc[mi][ni][2] + b0);
            atomicAdd(&C[(size_t)(row + 8) * N + col + 1], acc[mi][ni][3] + b1);
        }
    }
}

// ---------------- bf16 flash cross-attention: persistent, 2-stage pipeline ----------------
#define AST 24576
#define NWORK 480    // (LM/128) * NH * B
__global__ __launch_bounds__(256, 2) void attn_kernel(
    const __nv_bfloat16* __restrict__ qkv,
    const int* __restrict__ line_starts,
    const int* __restrict__ ctx_len,
    __nv_bfloat16* __restrict__ out)
{
    __shared__ __align__(16) char smem[2 * AST];

    int tid = threadIdx.x;
    int warp = tid >> 5, lane = tid & 31;
    uint32_t sb = s2u(smem);

    int r0 = warp * 16 + (lane >> 2);
    int c2 = (lane & 3) * 2;

    // ---- per-thread constants (work-independent) ----
    int frow[3], fcol[3], foff[3];
#pragma unroll
    for (int i = 0; i < 3; i++) {
        int u = tid + i * 256;
        frow[i] = u / 12; fcol[i] = u - frow[i] * 12;
        foff[i] = frow[i] * 192 + (fcol[i] ^ ((frow[i] >> 1) & 3)) * 16;
    }
    int sm = lane >> 3;
    int srow = (sm >> 1) * 8 + (lane & 7);
    int scb = sm & 1;
    int sprow[4], spsw[4];
#pragma unroll
    for (int np = 0; np < 4; np++) {
        int row = np * 16 + srow;
        sprow[np] = row * 192;
        spsw[np] = (row >> 1) & 3;
    }
    int vrow_b = (sm & 1) * 8 + (lane & 7);
    int vcb = sm >> 1;
    int vprow[4], vpsw[4];
#pragma unroll
    for (int ks = 0; ks < 4; ks++) {
        int row = ks * 16 + vrow_b;
        vprow[ks] = row * 192;
        vpsw[ks] = (row >> 1) & 3;
    }
    const unsigned bones[2] = {0x3F803F80u, 0x3F803F80u};

    for (int w = blockIdx.x; w < NWORK; w += gridDim.x) {
        int qi = w % 15;
        int h  = (w / 15) & 7;
        int b  = w / 120;
        int q0 = qi * 128;
        int ctx = ctx_len[b];

        // ---- Q fragments for this work unit ----
        const __nv_bfloat16 *qp0, *qp1;
        {
            int gq0 = q0 + r0;
            int l0i = gq0 / ML_, mm0 = gq0 - l0i * ML_;
            int pos0 = min(max(line_starts[b * L_ + l0i] + mm0, 0), S_ - 1);
            int gq1 = gq0 + 8;
            int l1i = gq1 / ML_, mm1 = gq1 - l1i * ML_;
            int pos1 = min(max(line_starts[b * L_ + l1i] + mm1, 0), S_ - 1);
            qp0 = qkv + ((size_t)b * S_ + pos0) * QKV_ + h * DH_;
            qp1 = qkv + ((size_t)b * S_ + pos1) * QKV_ + h * DH_;
        }
        unsigned qf[6][4];
#pragma unroll
        for (int ks = 0; ks < 6; ks++) {
            qf[ks][0] = *(const unsigned*)(qp0 + ks * 16 + c2);
            qf[ks][1] = *(const unsigned*)(qp1 + ks * 16 + c2);
            qf[ks][2] = *(const unsigned*)(qp0 + ks * 16 + c2 + 8);
            qf[ks][3] = *(const unsigned*)(qp1 + ks * 16 + c2 + 8);
        }

        const __nv_bfloat16* kbase = qkv + ((size_t)b * S_ + frow[0]) * QKV_ + H_ + h * DH_;
        const __nv_bfloat16 *kg[3], *vg[3];
#pragma unroll
        for (int i = 0; i < 3; i++) {
            kg[i] = qkv + ((size_t)b * S_ + frow[i]) * QKV_ + H_ + h * DH_ + fcol[i] * 8;
            vg[i] = kg[i] + H_;
        }
        (void)kbase;

        float Oacc[12][4], lacc[4];
#pragma unroll
        for (int nt = 0; nt < 12; nt++)
#pragma unroll
            for (int r = 0; r < 4; r++) Oacc[nt][r] = 0.0f;
#pragma unroll
        for (int r = 0; r < 4; r++) lacc[r] = 0.0f;

#define AFILL(st, s0f)                                                          \
        do {                                                                    \
            uint32_t kb_ = sb + (st) * AST;                                     \
            uint32_t vb_ = kb_ + 12288;                                         \
            _Pragma("unroll")                                                   \
            for (int i_ = 0; i_ < 3; i_++) {                                    \
                cpa16(kb_ + foff[i_], kg[i_] + (size_t)(s0f) * QKV_);           \
                cpa16(vb_ + foff[i_], vg[i_] + (size_t)(s0f) * QKV_);           \
            }                                                                   \
        } while (0)

        __syncthreads();   // previous unit's smem reads fully done
        AFILL(0, 0); CP_COMMIT();

        for (int ci = 0; ci < 32; ci++) {
            int s0 = ci * 64;
            if (ci < 31) AFILL((ci + 1) & 1, s0 + 64);
            CP_COMMIT();
            CP_WAIT1();
            __syncthreads();

            uint32_t Kst = sb + (ci & 1) * AST;
            uint32_t Vst = Kst + 12288;

            float sacc[8][4];
#pragma unroll
            for (int nt = 0; nt < 8; nt++)
#pragma unroll
                for (int r = 0; r < 4; r++) sacc[nt][r] = 0.0f;
#pragma unroll
            for (int ks = 0; ks < 6; ks++) {
#pragma unroll
                for (int np = 0; np < 4; np++) {
                    uint4 kb;
                    ldm4(kb, Kst + sprow[np] + ((2 * ks + scb) ^ spsw[np]) * 16);
                    mma_bf16(sacc[2 * np],     qf[ks], &kb.x);
                    mma_bf16(sacc[2 * np + 1], qf[ks], &kb.z);
                }
            }

            if (s0 + 64 > ctx) {
#pragma unroll
                for (int nt = 0; nt < 8; nt++) {
                    int t = s0 + nt * 8 + c2;
                    if (t >= ctx)     { sacc[nt][0] = -3e38f; sacc[nt][2] = -3e38f; }
                    if (t + 1 >= ctx) { sacc[nt][1] = -3e38f; sacc[nt][3] = -3e38f; }
                }
            }

#pragma unroll
            for (int ks = 0; ks < 4; ks++) {
                unsigned pa[4];
                pa[0] = bex2(pk(sacc[2 * ks][0],     sacc[2 * ks][1]));
                pa[1] = bex2(pk(sacc[2 * ks][2],     sacc[2 * ks][3]));
                pa[2] = bex2(pk(sacc[2 * ks + 1][0], sacc[2 * ks + 1][1]));
                pa[3] = bex2(pk(sacc[2 * ks + 1][2], sacc[2 * ks + 1][3]));
                mma_bf16(lacc, pa, bones);
#pragma unroll
                for (int np = 0; np < 6; np++) {
                    uint4 vb;
                    ldm4t(vb, Vst + vprow[ks] + ((2 * np + vcb) ^ vpsw[ks]) * 16);
                    mma_bf16(Oacc[2 * np],     pa, &vb.x);
                    mma_bf16(Oacc[2 * np + 1], pa, &vb.z);
                }
            }
            __syncthreads();
        }
#undef AFILL

        float inv0 = 1.0f / lacc[0];
        float inv1 = 1.0f / lacc[2];
#pragma unroll
        for (int nt = 0; nt < 12; nt++) {
            int col = h * DH_ + nt * 8 + c2;
            *(unsigned*)(out + ((size_t)b * LM_ + q0 + r0) * H_ + col) =
                pk(Oacc[nt][0] * inv0, Oacc[nt][1] * inv0);
            *(unsigned*)(out + ((size_t)b * LM_ + q0 + r0 + 8) * H_ + col) =
                pk(Oacc[nt][2] * inv1, Oacc[nt][3] * inv1);
        }
    }
}

// ---------------- masked mean-pool ----------------
__global__ __launch_bounds__(256) void pool_kernel(
    const float* __restrict__ hidden, const float* __restrict__ oproj,
    const int* __restrict__ line_starts, const int* __restrict__ line_lens,
    float* __restrict__ x)
{
    int bl = blockIdx.x;
    int b = bl / L_;
    int len = line_lens[bl];
    int start = line_starts[bl];
    float inv = 1.0f / (float)max(len, 1);
    for (int c = threadIdx.x; c < H_; c += 256) {
        float s1 = 0.0f, s2 = 0.0f;
        for (int m = 0; m < ML_; m++) {
            if (m < len) {
                int pos = min(max(start + m, 0), S_ - 1);
                s1 += hidden[((size_t)b * S_ + pos) * H_ + c];
                s2 += oproj[((size_t)bl * ML_ + m) * H_ + c];
            }
        }
        x[(size_t)bl * 2 * H_ + c]      = s1 * inv;
        x[(size_t)bl * 2 * H_ + H_ + c] = s2 * inv;
    }
}

// ---------------- LayerNorm -> exact GELU (+optional residual) ----------------
__global__ __launch_bounds__(256) void ln_gelu_kernel(
    const float* __restrict__ y, const float* __restrict__ g,
    const float* __restrict__ be, const float* __restrict__ res,
    float* __restrict__ out)
{
    __shared__ float red1[8], red2[8];
    int row = blockIdx.x;
    const float* yr = y + (size_t)row * H_;
    float v[3], sum = 0.0f, sq = 0.0f;
#pragma unroll
    for (int i = 0; i < 3; i++) {
        v[i] = yr[threadIdx.x + 256 * i];
        sum += v[i];
        sq  += v[i] * v[i];
    }
#pragma unroll
    for (int o = 16; o > 0; o >>= 1) {
        sum += __shfl_xor_sync(0xffffffffu, sum, o);
        sq  += __shfl_xor_sync(0xffffffffu, sq,  o);
    }
    int warp = threadIdx.x >> 5;
    if ((threadIdx.x & 31) == 0) { red1[warp] = sum; red2[warp] = sq; }
    __syncthreads();
    float tsum = 0.0f, tsq = 0.0f;
#pragma unroll
    for (int i = 0; i < 8; i++) { tsum += red1[i]; tsq += red2[i]; }
    float mean = tsum * (1.0f / H_);
    float var  = tsq  * (1.0f / H_) - mean * mean;
    float rstd = rsqrtf(var + 1e-5f);
#pragma unroll
    for (int i = 0; i < 3; i++) {
        int c = threadIdx.x + 256 * i;
        float t  = (v[i] - mean) * rstd * g[c] + be[c];
        float ge = 0.5f * t * (1.0f + erff(t * 0.70710678118654752f));
        out[(size_t)row * H_ + c] = (res ? res[(size_t)row * H_ + c] : 0.0f) + ge;
    }
}

// ---------------- final logit ----------------
__global__ __launch_bounds__(128) void final_kernel(
    const float* __restrict__ a2, const float* __restrict__ W3,
    const float* __restrict__ b3, const int* __restrict__ line_lens,
    float* __restrict__ out)
{
    int row  = blockIdx.x * 4 + (threadIdx.x >> 5);
    int lane = threadIdx.x & 31;
    float s = 0.0f;
    for (int c = lane; c < H_; c += 32)
        s += a2[(size_t)row * H_ + c] * W3[c];
#pragma unroll
    for (int o = 16; o > 0; o >>= 1) s += __shfl_xor_sync(0xffffffffu, s, o);
    if (lane == 0) {
        float logit = s + b3[0];
        if (line_lens[row] <= 0) logit = -10.0f;
        out[row] = 1.0f / (1.0f + __expf(-logit));
    }
}

// ---------------- launch ----------------
extern "C" void kernel_launch(void* const* d_in, const int* in_sizes, int n_in,
                              void* d_out, int out_size)
{
    (void)in_sizes; (void)n_in; (void)out_size;
    const float* hidden  = (const float*)d_in[0];
    const float* in_w    = (const float*)d_in[1];
    const float* in_b    = (const float*)d_in[2];
    const float* out_w   = (const float*)d_in[3];
    const float* out_b   = (const float*)d_in[4];
    const float* W1      = (const float*)d_in[5];
    const float* b1      = (const float*)d_in[6];
    const float* g1      = (const float*)d_in[7];
    const float* be1     = (const float*)d_in[8];
    const float* W2      = (const float*)d_in[9];
    const float* b2      = (const float*)d_in[10];
    const float* g2      = (const float*)d_in[11];
    const float* be2     = (const float*)d_in[12];
    const float* W3      = (const float*)d_in[13];
    const float* b3      = (const float*)d_in[14];
    const int*   lstarts = (const int*)d_in[15];
    const int*   llens   = (const int*)d_in[16];
    const int*   ctx     = (const int*)d_in[17];
    float* out = (float*)d_out;

    __nv_bfloat16 *hb, *wib, *wob, *qkvh, *atnh;
    float *oproj, *x, *y1, *y2;
    cudaGetSymbolAddress((void**)&hb,    g_hb);
    cudaGetSymbolAddress((void**)&wib,   g_wib);
    cudaGetSymbolAddress((void**)&wob,   g_wob);
    cudaGetSymbolAddress((void**)&qkvh,  g_qkvh);
    cudaGetSymbolAddress((void**)&atnh,  g_atnh);
    cudaGetSymbolAddress((void**)&oproj, g_oproj);
    cudaGetSymbolAddress((void**)&x,     g_x);
    cudaGetSymbolAddress((void**)&y1,    g_y1);
    cudaGetSymbolAddress((void**)&y2,    g_y2);

    const float qmul = 0.10206207261596577f * 1.4426950408889634f;  // 1/sqrt(96)*log2e

    // 0) one-time f32->bf16 converts + zero split-K outputs
    f2b_kernel<<<2048, 256>>>(hidden, hb,  (B_ * S_ * H_) / 2);
    f2b_kernel<<<1024, 256>>>(in_w,  wib, (QKV_ * H_) / 2);
    f2b_kernel<<<512,  256>>>(out_w, wob, (H_ * H_) / 2);
    cudaMemsetAsync(y1, 0, (size_t)B_ * L_ * H_ * sizeof(float));
    cudaMemsetAsync(y2, 0, (size_t)B_ * L_ * H_ * sizeof(float));

    // 1) QKV projection (bf16 out, Q columns pre-scaled)
    gemm_bf16_cp<<<dim3(QKV_ / 128, (B_ * S_) / 128), 256>>>(
        hb, wib, in_b, qkvh, B_ * S_, QKV_, H_, 1, qmul, H_);
    // 2) cross attention (persistent: 296 CTAs over 480 work units)
    attn_kernel<<<296, 256>>>(qkvh, lstarts, ctx, atnh);
    // 3) out_proj (bf16 in, f32 out)
    gemm_bf16_cp<<<dim3(H_ / 128, (B_ * LM_) / 128), 256>>>(
        atnh, wob, out_b, oproj, B_ * LM_, H_, H_, 0, 1.0f, 0);
    // 4) pooled features
    pool_kernel<<<B_ * L_, 256>>>(hidden, oproj, lstarts, llens, x);
    // 5) classifier head (tf32, split-K x4)
    gemm_tf32_sk<<<dim3(H_ / 128, (B_ * L_) / 128, 4), 256>>>(
        x, W1, b1, y1, B_ * L_, H_, 2 * H_, 2 * H_ / 4);
    ln_gelu_kernel<<<B_ * L_, 256>>>(y1, g1, be1, nullptr, y1);
    gemm_tf32_sk<<<dim3(H_ / 128, (B_ * L_) / 128, 4), 256>>>(
        y1, W2, b2, y2, B_ * L_, H_, H_, H_ / 4);
    ln_gelu_kernel<<<B_ * L_, 256>>>(y2, g2, be2, y1, y2);
    final_kernel<<<B_ * L_ / 4, 128>>>(y2, W3, b3, llens, out);
}